// round 5
// baseline (speedup 1.0000x reference)
#include <cuda_runtime.h>
#include <cuda_bf16.h>
#include <cstdint>
#include <math.h>

// ---------------------------------------------------------------------------
#define NN 8192
#define DD 768
#define BT 128                    // square CTA tile
#define NRB (NN / BT)             // 64 row/col strips
#define BK 32                     // k per stage (64B rows)
#define NCH (DD / BK)             // 24 k-chunks
#define STAGES 4
#define TILE_BYTES 8192           // one 128x32 bf16 tile, contiguous + pre-swizzled
#define STAGE_BYTES (2 * TILE_BYTES)
#define NTRI (NRB * (NRB + 1) / 2)   // 2080 CTAs
#define NP NRB                    // 64 partials per row
#define NEG_BIG (-1.0e30f)

// Scratch (no allocations allowed)
__device__ __align__(256) unsigned char g_xt[(size_t)NRB * NCH * TILE_BYTES]; // tiled bf16 X
__device__ float g_sq[NN];
__device__ float g_pm[NN * NP];
__device__ float g_pz[NN * NP];
__device__ float g_pt[NN * NP];

// ---------------------------------------------------------------------------
__device__ __forceinline__ uint32_t smem_u32(const void* p) {
    uint32_t a;
    asm("{ .reg .u64 t; cvta.to.shared.u64 t, %1; cvt.u32.u64 %0, t; }" : "=r"(a) : "l"(p));
    return a;
}
// 64B-row swizzle: XOR bits[5:4] with row bits[2:1] (row = off>>6)
__device__ __forceinline__ uint32_t sw64(uint32_t off) {
    return off ^ (((off >> 7) & 3u) << 4);
}
#define MBARRIER_INIT(addr, cnt) \
    asm volatile("mbarrier.init.shared.b64 [%0], %1;" :: "r"((uint32_t)(addr)), "r"((uint32_t)(cnt)) : "memory")
#define MBARRIER_EXPECT_TX(addr, bytes) \
    asm volatile("mbarrier.arrive.expect_tx.shared.b64 _, [%0], %1;" :: "r"((uint32_t)(addr)), "r"((uint32_t)(bytes)) : "memory")
#define MBARRIER_WAIT_PARITY(addr, par) do {                                   \
    uint32_t _mb = (uint32_t)(addr);                                           \
    uint32_t _pa = (uint32_t)(par);                                            \
    uint32_t _dn;                                                              \
    asm volatile(                                                              \
        "{\n\t.reg .pred p;\n\t"                                               \
        "mbarrier.try_wait.parity.acquire.cta.shared::cta.b64 p, [%1], %2;\n\t"\
        "selp.b32 %0, 1, 0, p;\n\t}"                                           \
        : "=r"(_dn) : "r"(_mb), "r"(_pa) : "memory");                          \
    if (!_dn) {                                                                \
        asm volatile(                                                          \
            "{\n\t.reg .pred P1;\n\t"                                          \
            "WL_%=:\n\t"                                                       \
            "mbarrier.try_wait.parity.acquire.cta.shared::cta.b64 P1, [%0], %1, 0x989680;\n\t" \
            "@P1 bra.uni WD_%=;\n\t"                                           \
            "bra.uni WL_%=;\n\t"                                               \
            "WD_%=:\n\t}"                                                      \
            :: "r"(_mb), "r"(_pa) : "memory");                                 \
    }                                                                          \
} while (0)

__device__ __forceinline__ void bulk_copy(uint32_t dst, const void* src, uint32_t bytes,
                                          uint32_t mbar) {
    asm volatile(
        "cp.async.bulk.shared::cluster.global.mbarrier::complete_tx::bytes [%0], [%1], %2, [%3];"
        :: "r"(dst), "l"(src), "r"(bytes), "r"(mbar) : "memory");
}
__device__ __forceinline__ void ldsm_x4(uint32_t& r0, uint32_t& r1, uint32_t& r2, uint32_t& r3,
                                        uint32_t addr) {
    asm volatile("ldmatrix.sync.aligned.m8n8.x4.shared.b16 {%0,%1,%2,%3}, [%4];"
                 : "=r"(r0), "=r"(r1), "=r"(r2), "=r"(r3) : "r"(addr));
}
__device__ __forceinline__ void mma16816(float* d, const uint32_t* a, uint32_t b0, uint32_t b1) {
    asm volatile(
        "mma.sync.aligned.m16n8k16.row.col.f32.bf16.bf16.f32 "
        "{%0,%1,%2,%3}, {%4,%5,%6,%7}, {%8,%9}, {%0,%1,%2,%3};"
        : "+f"(d[0]), "+f"(d[1]), "+f"(d[2]), "+f"(d[3])
        : "r"(a[0]), "r"(a[1]), "r"(a[2]), "r"(a[3]), "r"(b0), "r"(b1));
}
__device__ __forceinline__ void merge_stats(float& m, float& z, float& t,
                                            float m2, float z2, float t2) {
    float mn = fmaxf(m, m2);
    float d1 = m - mn, d2 = m2 - mn;
    float a = __expf(d1), b = __expf(d2);
    t = a * (t + d1 * z) + b * (t2 + d2 * z2);
    z = a * z + b * z2;
    m = mn;
}

// ---------------------------------------------------------------------------
// Kernel 1: f32 -> bf16, repacked into contiguous pre-swizzled 8KB tiles,
// plus row squared norms. 192 threads = one row, 4 floats each.
__global__ void prep_kernel(const float* __restrict__ x) {
    const int row = blockIdx.x;
    const int t = threadIdx.x;            // 0..191
    const int k0 = 4 * t;
    float4 v = reinterpret_cast<const float4*>(x + (size_t)row * DD)[t];
    float s = v.x * v.x + v.y * v.y + v.z * v.z + v.w * v.w;
    uint32_t p0, p1;
    {
        __nv_bfloat162 b0, b1;
        b0.x = __float2bfloat16(v.x); b0.y = __float2bfloat16(v.y);
        b1.x = __float2bfloat16(v.z); b1.y = __float2bfloat16(v.w);
        p0 = *reinterpret_cast<uint32_t*>(&b0);
        p1 = *reinterpret_cast<uint32_t*>(&b1);
    }
    const uint32_t tile = (uint32_t)(row >> 7) * NCH + (k0 >> 5);
    uint32_t off = (uint32_t)((row & 127) * 64 + (k0 & 31) * 2);
    off = sw64(off);
    *reinterpret_cast<uint2*>(g_xt + (size_t)tile * TILE_BYTES + off) = make_uint2(p0, p1);

#pragma unroll
    for (int o = 16; o > 0; o >>= 1) s += __shfl_down_sync(0xffffffffu, s, o);
    __shared__ float ws[6];
    int wid = t >> 5, lane = t & 31;
    if (lane == 0) ws[wid] = s;
    __syncthreads();
    if (t == 0) {
        float tot = 0.f;
#pragma unroll
        for (int i = 0; i < 6; ++i) tot += ws[i];
        g_sq[row] = tot;
    }
}

// ---------------------------------------------------------------------------
// Kernel 2: upper-triangle 128x128 Gram tiles via bf16 HMMA + bulk-copy
// pipeline; fused row-stats AND transposed col-stats (symmetry).
// 512 threads = 16 warps (4m x 4n), warp tile 32x32.
// Pipeline: full-mbarrier per stage + __syncthreads() before refill (at most
// one outstanding phase per barrier -> no parity wrap possible).
__global__ __launch_bounds__(512, 1)
void main_kernel(const float* __restrict__ tau_p) {
    extern __shared__ char smem[];
    __shared__ __align__(8) uint64_t mbars[STAGES];       // full[4]
    __shared__ float scratch[3 * BT * 4];                 // [128][4] x {m,z,t}

    const uint32_t sb = smem_u32(smem);
    const int tid = threadIdx.x;
    const int wid = tid >> 5;
    const int lane = tid & 31;
    const int warp_m = wid & 3;
    const int warp_n = wid >> 2;

    // Triangle decode: blockIdx.x -> (rb, cb), rb <= cb
    int rb;
    {
        const int t = blockIdx.x;
        float f = (2 * NRB + 1 - sqrtf((float)((2 * NRB + 1) * (2 * NRB + 1) - 8 * t))) * 0.5f;
        rb = (int)f;
        if (rb > NRB - 1) rb = NRB - 1;
        while (rb * NRB - rb * (rb - 1) / 2 > t) --rb;
        while ((rb + 1) * NRB - (rb + 1) * rb / 2 <= t) ++rb;
    }
    const int cb = rb + ((int)blockIdx.x - (rb * NRB - rb * (rb - 1) / 2));
    const int rbase = rb * BT;
    const int cbase = cb * BT;

#define MB_FULL(s) (smem_u32(&mbars[(s)]))

    if (tid == 0) {
#pragma unroll
        for (int s = 0; s < STAGES; ++s) MBARRIER_INIT(MB_FULL(s), 1);
    }
    __syncthreads();

    // Prologue: issue all STAGES stages
    if (tid == 0) {
#pragma unroll
        for (int s = 0; s < STAGES; ++s) {
            MBARRIER_EXPECT_TX(MB_FULL(s), STAGE_BYTES);
            bulk_copy(sb + s * STAGE_BYTES,
                      g_xt + (size_t)(rb * NCH + s) * TILE_BYTES, TILE_BYTES, MB_FULL(s));
            bulk_copy(sb + s * STAGE_BYTES + TILE_BYTES,
                      g_xt + (size_t)(cb * NCH + s) * TILE_BYTES, TILE_BYTES, MB_FULL(s));
        }
    }

    float acc[2][4][4];
#pragma unroll
    for (int mt = 0; mt < 2; ++mt)
#pragma unroll
        for (int nt = 0; nt < 4; ++nt)
#pragma unroll
            for (int e = 0; e < 4; ++e) acc[mt][nt][e] = 0.f;

    const int lr = lane & 15;
    const int lc = (lane >> 4) * 16;

#pragma unroll 1
    for (int kc = 0; kc < NCH; ++kc) {
        const int s = kc & (STAGES - 1);
        MBARRIER_WAIT_PARITY(MB_FULL(s), (kc >> 2) & 1);
        const uint32_t sA = sb + s * STAGE_BYTES;
        const uint32_t sB = sA + TILE_BYTES;
#pragma unroll
        for (int kk = 0; kk < 2; ++kk) {
            uint32_t a[2][4], b[2][4];
#pragma unroll
            for (int mt = 0; mt < 2; ++mt)
                ldsm_x4(a[mt][0], a[mt][1], a[mt][2], a[mt][3],
                        sA + sw64((uint32_t)((warp_m * 32 + mt * 16 + lr) * 64 + kk * 32 + lc)));
#pragma unroll
            for (int np = 0; np < 2; ++np)
                ldsm_x4(b[np][0], b[np][1], b[np][2], b[np][3],
                        sB + sw64((uint32_t)((warp_n * 32 + np * 16 + lr) * 64 + kk * 32 + lc)));
#pragma unroll
            for (int mt = 0; mt < 2; ++mt)
#pragma unroll
                for (int nt = 0; nt < 4; ++nt)
                    mma16816(acc[mt][nt], a[mt], b[nt >> 1][nt & 1], b[nt >> 1][2 + (nt & 1)]);
        }
        // All warps done reading stage s before it is refilled (no parity wrap:
        // at most one outstanding phase per mbarrier).
        __syncthreads();
        if (tid == 0) {
            const int next = kc + STAGES;
            if (next < NCH) {
                MBARRIER_EXPECT_TX(MB_FULL(s), STAGE_BYTES);
                bulk_copy(sb + s * STAGE_BYTES,
                          g_xt + (size_t)(rb * NCH + next) * TILE_BYTES, TILE_BYTES, MB_FULL(s));
                bulk_copy(sb + s * STAGE_BYTES + TILE_BYTES,
                          g_xt + (size_t)(cb * NCH + next) * TILE_BYTES, TILE_BYTES, MB_FULL(s));
            }
        }
    }

    // ---------------- epilogue ----------------
    const float tau = *tau_p;
    const float two_tau = 2.0f * tau;
    const float dpen = -100.0f * tau;

    float* sm_m = scratch;
    float* sm_z = scratch + BT * 4;
    float* sm_t = scratch + 2 * BT * 4;

    // ---- pass 1: row stats (rows in rb strip, cols in cb strip) ----
    float tsqc[8];
#pragma unroll
    for (int nt = 0; nt < 4; ++nt)
#pragma unroll
        for (int e0 = 0; e0 < 2; ++e0)
            tsqc[nt * 2 + e0] = tau * g_sq[cbase + warp_n * 32 + nt * 8 + (lane & 3) * 2 + e0];

#pragma unroll
    for (int mt = 0; mt < 2; ++mt) {
#pragma unroll
        for (int hf = 0; hf < 2; ++hf) {
            const int rrow = warp_m * 32 + mt * 16 + (lane >> 2) + hf * 8;
            const int grow = rbase + rrow;
            float lv[8];
            float cm = NEG_BIG;
#pragma unroll
            for (int nt = 0; nt < 4; ++nt)
#pragma unroll
                for (int e0 = 0; e0 < 2; ++e0) {
                    const int gcol = cbase + warp_n * 32 + nt * 8 + (lane & 3) * 2 + e0;
                    float l = fmaf(two_tau, acc[mt][nt][hf * 2 + e0], -tsqc[nt * 2 + e0]);
                    if (gcol == grow) l += dpen;
                    lv[nt * 2 + e0] = l;
                    cm = fmaxf(cm, l);
                }
            float z = 0.f, tt = 0.f;
#pragma unroll
            for (int j = 0; j < 8; ++j) {
                float d = lv[j] - cm;
                float e = __expf(d);
                z += e;
                tt = fmaf(d, e, tt);
            }
#pragma unroll
            for (int o = 1; o < 4; o <<= 1) {
                float mo = __shfl_xor_sync(0xffffffffu, cm, o);
                float zo = __shfl_xor_sync(0xffffffffu, z,  o);
                float to = __shfl_xor_sync(0xffffffffu, tt, o);
                merge_stats(cm, z, tt, mo, zo, to);
            }
            if ((lane & 3) == 0) {
                sm_m[rrow * 4 + warp_n] = cm;
                sm_z[rrow * 4 + warp_n] = z;
                sm_t[rrow * 4 + warp_n] = tt;
            }
        }
    }
    __syncthreads();
    if (tid < BT) {
        float m = NEG_BIG, z = 0.f, tt = 0.f;
#pragma unroll
        for (int w = 0; w < 4; ++w)
            merge_stats(m, z, tt, sm_m[tid * 4 + w], sm_z[tid * 4 + w], sm_t[tid * 4 + w]);
        const int grow = rbase + tid;
        g_pm[grow * NP + cb] = m;
        g_pz[grow * NP + cb] = z;
        g_pt[grow * NP + cb] = tt;
    }

    // ---- pass 2: transposed col stats (rows in cb strip, cols in rb strip) ----
    if (rb != cb) {
        __syncthreads();
        float tsqr[4];
#pragma unroll
        for (int mt = 0; mt < 2; ++mt)
#pragma unroll
            for (int hf = 0; hf < 2; ++hf)
                tsqr[mt * 2 + hf] = tau * g_sq[rbase + warp_m * 32 + mt * 16 + (lane >> 2) + hf * 8];

#pragma unroll
        for (int nt = 0; nt < 4; ++nt) {
#pragma unroll
            for (int e0 = 0; e0 < 2; ++e0) {
                float cm = NEG_BIG;
                float lv[4];
#pragma unroll
                for (int mt = 0; mt < 2; ++mt)
#pragma unroll
                    for (int hf = 0; hf < 2; ++hf) {
                        float l = fmaf(two_tau, acc[mt][nt][hf * 2 + e0], -tsqr[mt * 2 + hf]);
                        lv[mt * 2 + hf] = l;
                        cm = fmaxf(cm, l);
                    }
                float z = 0.f, tt = 0.f;
#pragma unroll
                for (int j = 0; j < 4; ++j) {
                    float d = lv[j] - cm;
                    float e = __expf(d);
                    z += e;
                    tt = fmaf(d, e, tt);
                }
#pragma unroll
                for (int o = 4; o < 32; o <<= 1) {
                    float mo = __shfl_xor_sync(0xffffffffu, cm, o);
                    float zo = __shfl_xor_sync(0xffffffffu, z,  o);
                    float to = __shfl_xor_sync(0xffffffffu, tt, o);
                    merge_stats(cm, z, tt, mo, zo, to);
                }
                if (lane < 4) {
                    const int col = warp_n * 32 + nt * 8 + (lane & 3) * 2 + e0;
                    sm_m[col * 4 + warp_m] = cm;
                    sm_z[col * 4 + warp_m] = z;
                    sm_t[col * 4 + warp_m] = tt;
                }
            }
        }
        __syncthreads();
        if (tid < BT) {
            float m = NEG_BIG, z = 0.f, tt = 0.f;
#pragma unroll
            for (int w = 0; w < 4; ++w)
                merge_stats(m, z, tt, sm_m[tid * 4 + w], sm_z[tid * 4 + w], sm_t[tid * 4 + w]);
            const int grow = cbase + tid;
            g_pm[grow * NP + rb] = m;
            g_pz[grow * NP + rb] = z;
            g_pt[grow * NP + rb] = tt;
        }
    }
}

// ---------------------------------------------------------------------------
// Kernel 3: merge column partials -> entropy -> mean -> scale by coef
__global__ void finalize_kernel(const float* __restrict__ coef_p, float* __restrict__ out) {
    const int tid = threadIdx.x;
    float acc = 0.f;
    for (int rr = tid; rr < NN; rr += 1024) {
        float m = NEG_BIG, z = 0.f, t = 0.f;
#pragma unroll
        for (int s = 0; s < NP; ++s)
            merge_stats(m, z, t, g_pm[rr * NP + s], g_pz[rr * NP + s], g_pt[rr * NP + s]);
        acc += logf(z) - t / z;
    }
#pragma unroll
    for (int o = 16; o > 0; o >>= 1) acc += __shfl_down_sync(0xffffffffu, acc, o);
    __shared__ float ws[32];
    int wid = tid >> 5, lane = tid & 31;
    if (lane == 0) ws[wid] = acc;
    __syncthreads();
    if (tid == 0) {
        float tot = 0.f;
#pragma unroll
        for (int i = 0; i < 32; ++i) tot += ws[i];
        out[0] = coef_p[0] * (tot / (float)NN);
    }
}

// ---------------------------------------------------------------------------
extern "C" void kernel_launch(void* const* d_in, const int* in_sizes, int n_in,
                              void* d_out, int out_size) {
    (void)in_sizes; (void)n_in; (void)out_size;
    const float* x    = (const float*)d_in[0];
    const float* coef = (const float*)d_in[1];
    const float* tau  = (const float*)d_in[2];
    float* out = (float*)d_out;

    prep_kernel<<<NN, 192>>>(x);

    cudaFuncSetAttribute(main_kernel, cudaFuncAttributeMaxDynamicSharedMemorySize,
                         STAGES * STAGE_BYTES);
    main_kernel<<<NTRI, 512, STAGES * STAGE_BYTES>>>(tau);

    finalize_kernel<<<1, 1024>>>(coef, out);
}